// round 9
// baseline (speedup 1.0000x reference)
#include <cuda_runtime.h>
#include <cstdint>

#define TPB 128
typedef unsigned long long u64;

// ---- Blackwell packed f32x2 FMA (ptxas never auto-fuses this) ----
__device__ __forceinline__ u64 ffma2(u64 a, u64 b, u64 c) {
    u64 d;
    asm("fma.rn.f32x2 %0, %1, %2, %3;" : "=l"(d) : "l"(a), "l"(b), "l"(c));
    return d;
}
__device__ __forceinline__ u64 pack2(float lo, float hi) {
    u64 d;
    unsigned a = __float_as_uint(lo), b = __float_as_uint(hi);
    asm("mov.b64 %0, {%1,%2};" : "=l"(d) : "r"(a), "r"(b));
    return d;
}
__device__ __forceinline__ u64 dup2(float v) {
    u64 d;
    unsigned a = __float_as_uint(v);
    asm("mov.b64 %0, {%1,%1};" : "=l"(d) : "r"(a));
    return d;
}
__device__ __forceinline__ void unpack2(u64 d, float& lo, float& hi) {
    unsigned a, b;
    asm("mov.b64 {%0,%1}, %2;" : "=r"(a), "=r"(b) : "l"(d));
    lo = __uint_as_float(a);
    hi = __uint_as_float(b);
}
__device__ __forceinline__ float tanh_fast(float v) {
    float r;
    asm("tanh.approx.f32 %0, %1;" : "=f"(r) : "f"(v));
    return r;
}
template<int OFF>
__device__ __forceinline__ float lds32(unsigned a) {
    float v;
    asm volatile("ld.shared.f32 %0, [%1+%2];" : "=f"(v) : "r"(a), "n"(OFF));
    return v;
}
__device__ __forceinline__ void cp16(unsigned dst, const void* src) {
    asm volatile("cp.async.cg.shared.global [%0], [%1], 16;"
                 :: "r"(dst), "l"(src) : "memory");
}
__device__ __forceinline__ void cp_commit() {
    asm volatile("cp.async.commit_group;" ::: "memory");
}
__device__ __forceinline__ void cp_wait_all() {
    asm volatile("cp.async.wait_group 0;" ::: "memory");
}

// W1 chain for one row: 8 broadcast z loads, in-register dup, 32 packed FMAs
// into 4 feature-packed accumulators. (Epilogue kept separate so the
// scheduler can interleave it with the NEXT row's chain.)
template<int RO>
__device__ __forceinline__ void w1_chain(unsigned za,
                                         const u64 (&w1p)[8][4],
                                         const u64 (&b1p)[4],
                                         u64 (&a)[4])
{
    float f0 = lds32<RO +  0>(za);
    float f1 = lds32<RO +  4>(za);
    float f2 = lds32<RO +  8>(za);
    float f3 = lds32<RO + 12>(za);
    float f4 = lds32<RO + 16>(za);
    float f5 = lds32<RO + 20>(za);
    float f6 = lds32<RO + 24>(za);
    float f7 = lds32<RO + 28>(za);

    u64 z0 = dup2(f0), z1 = dup2(f1), z2 = dup2(f2), z3 = dup2(f3);
    u64 z4 = dup2(f4), z5 = dup2(f5), z6 = dup2(f6), z7 = dup2(f7);

    a[0] = ffma2(z0, w1p[0][0], b1p[0]);
    a[1] = ffma2(z0, w1p[0][1], b1p[1]);
    a[2] = ffma2(z0, w1p[0][2], b1p[2]);
    a[3] = ffma2(z0, w1p[0][3], b1p[3]);
    a[0] = ffma2(z1, w1p[1][0], a[0]); a[1] = ffma2(z1, w1p[1][1], a[1]);
    a[2] = ffma2(z1, w1p[1][2], a[2]); a[3] = ffma2(z1, w1p[1][3], a[3]);
    a[0] = ffma2(z2, w1p[2][0], a[0]); a[1] = ffma2(z2, w1p[2][1], a[1]);
    a[2] = ffma2(z2, w1p[2][2], a[2]); a[3] = ffma2(z2, w1p[2][3], a[3]);
    a[0] = ffma2(z3, w1p[3][0], a[0]); a[1] = ffma2(z3, w1p[3][1], a[1]);
    a[2] = ffma2(z3, w1p[3][2], a[2]); a[3] = ffma2(z3, w1p[3][3], a[3]);
    a[0] = ffma2(z4, w1p[4][0], a[0]); a[1] = ffma2(z4, w1p[4][1], a[1]);
    a[2] = ffma2(z4, w1p[4][2], a[2]); a[3] = ffma2(z4, w1p[4][3], a[3]);
    a[0] = ffma2(z5, w1p[5][0], a[0]); a[1] = ffma2(z5, w1p[5][1], a[1]);
    a[2] = ffma2(z5, w1p[5][2], a[2]); a[3] = ffma2(z5, w1p[5][3], a[3]);
    a[0] = ffma2(z6, w1p[6][0], a[0]); a[1] = ffma2(z6, w1p[6][1], a[1]);
    a[2] = ffma2(z6, w1p[6][2], a[2]); a[3] = ffma2(z6, w1p[6][3], a[3]);
    a[0] = ffma2(z7, w1p[7][0], a[0]); a[1] = ffma2(z7, w1p[7][1], a[1]);
    a[2] = ffma2(z7, w1p[7][2], a[2]); a[3] = ffma2(z7, w1p[7][3], a[3]);
}

// tanh + packed W2 dot for one row's accumulators -> partial y (this fg)
__device__ __forceinline__ float epi(const u64 (&a)[4],
                                     const u64 (&w2p)[4],
                                     u64 biaspack)
{
    float h0, h1, h2, h3, h4, h5, h6, h7;
    unpack2(a[0], h0, h1); unpack2(a[1], h2, h3);
    unpack2(a[2], h4, h5); unpack2(a[3], h6, h7);
    h0 = tanh_fast(h0); h1 = tanh_fast(h1);
    h2 = tanh_fast(h2); h3 = tanh_fast(h3);
    h4 = tanh_fast(h4); h5 = tanh_fast(h5);
    h6 = tanh_fast(h6); h7 = tanh_fast(h7);
    u64 yp = ffma2(pack2(h0, h1), w2p[0], biaspack);
    yp = ffma2(pack2(h2, h3), w2p[1], yp);
    yp = ffma2(pack2(h4, h5), w2p[2], yp);
    yp = ffma2(pack2(h6, h7), w2p[3], yp);
    float lo, hi;
    unpack2(yp, lo, hi);
    return lo + hi;
}

__global__ void __launch_bounds__(TPB, 4)
fans_kernel(const float* __restrict__ x,
            const float* __restrict__ W1,
            const float* __restrict__ b1,
            const float* __restrict__ W2,
            const float* __restrict__ b2,
            float* __restrict__ out,
            int ntiles)
{
    // RAW x tile: 32 rows x 40 cols fp32 (slots 32..39 mirror cols 0..7 so
    // every neuron's window cols n..n+7 is contiguous). Double-buffered.
    __shared__ __align__(16) float xs[2][32][40];   // 10 KB

    const int tid  = threadIdx.x;
    const int lane = tid & 31;
    const int warp = tid >> 5;
    const int nl   = lane & 7;
    const int fg   = lane >> 3;       // 0..3, feature group of 8
    const int n    = warp * 8 + nl;   // neuron 0..31

    // ---- register-resident weight slice (loaded once) ----
    // window position t reads col (n+t)%32; sorted (np.nonzero) order maps
    // that to k = (t + wrap) % 8, wrap = max(0, n+8-32): pre-rotate W1.
    const int wrapc = (n + 8 > 32) ? (n + 8 - 32) : 0;
    u64 w1p[8][4];
    #pragma unroll
    for (int t = 0; t < 8; t++) {
        int k = t + wrapc;
        if (k >= 8) k -= 8;
        const float* wp = W1 + n * 256 + k * 32 + fg * 8;
        ulonglong2 a = *(const ulonglong2*)wp;
        ulonglong2 b = *(const ulonglong2*)(wp + 4);
        w1p[t][0] = a.x; w1p[t][1] = a.y; w1p[t][2] = b.x; w1p[t][3] = b.y;
    }
    u64 b1p[4];
    {
        const float* bp = b1 + n * 32 + fg * 8;
        ulonglong2 a = *(const ulonglong2*)bp;
        ulonglong2 b = *(const ulonglong2*)(bp + 4);
        b1p[0] = a.x; b1p[1] = a.y; b1p[2] = b.x; b1p[3] = b.y;
    }
    u64 w2p[4];
    {
        const float* wp = W2 + n * 32 + fg * 8;
        ulonglong2 a = *(const ulonglong2*)wp;
        ulonglong2 b = *(const ulonglong2*)(wp + 4);
        w2p[0] = a.x; w2p[1] = a.y; w2p[2] = b.x; w2p[3] = b.y;
    }
    const u64 biaspack = pack2((fg == 0) ? b2[n] : 0.0f, 0.0f);
    const bool fb0 = (fg & 1) != 0;

    unsigned sbase;
    asm("{ .reg .u64 t; cvta.to.shared.u64 t, %1; cvt.u32.u64 %0, t; }"
        : "=r"(sbase) : "l"(&xs[0][0][0]));
    const unsigned zb = sbase + (unsigned)(n * 4);   // window base = col n

    int tile = blockIdx.x;
    if (tile >= ntiles) return;
    const char* gxb = (const char*)x;

    // staging map (cp.async, 16B granules):
    //   main: thread covers float4 chunks m0=2*tid, m0+1 of the 32x32 tile
    //   wrap: threads 0..63 copy cols 0..7 of each row into slots 32..39
    const int m0 = tid * 2;
    const unsigned d0 = (unsigned)((m0 >> 3) * 160 + (m0 & 7) * 16);
    const unsigned d1 = (unsigned)(((m0 + 1) >> 3) * 160 + ((m0 + 1) & 7) * 16);
    const unsigned dw = (unsigned)((tid >> 1) * 160 + 128 + (tid & 1) * 16);
    const unsigned g0 = (unsigned)(m0 * 16);
    const unsigned g1 = (unsigned)((m0 + 1) * 16);
    const unsigned gw = (unsigned)((tid >> 1) * 128 + (tid & 1) * 16);

    // ---- stage first tile ----
    {
        const char* src = gxb + (size_t)tile * 4096;
        cp16(sbase + d0, src + g0);
        cp16(sbase + d1, src + g1);
        if (tid < 64) cp16(sbase + dw, src + gw);
        cp_commit();
    }
    cp_wait_all();
    __syncthreads();

    int buf = 0;
    for (;;) {
        const int next = tile + gridDim.x;
        const bool have_next = next < ntiles;
        if (have_next) {
            const unsigned sb = sbase + (unsigned)((buf ^ 1) * 5120);
            const char* src = gxb + (size_t)next * 4096;
            cp16(sb + d0, src + g0);
            cp16(sb + d1, src + g1);
            if (tid < 64) cp16(sb + dw, src + gw);
            cp_commit();
        }

        // ---- compute 32 rows, software-pipelined in pairs:
        //      while chaining pair g, run epilogue of pair g-1 ----
        // store lanes: lane<16, row within pair = fg&1
        float* op = out + (size_t)tile * 1024 + (fg & 1) * 32 + n;
        unsigned za = zb + (unsigned)(buf * 5120);

        u64 A0[4], A1[4];
        w1_chain<0>  (za, w1p, b1p, A0);
        w1_chain<160>(za, w1p, b1p, A1);
        za += 320;

        #pragma unroll 2
        for (int g = 1; g < 16; g++) {
            u64 B0[4], B1[4];
            w1_chain<0>(za, w1p, b1p, B0);
            float y0 = epi(A0, w2p, biaspack);       // overlaps chain B0/B1
            w1_chain<160>(za, w1p, b1p, B1);
            float y1 = epi(A1, w2p, biaspack);

            // pair transpose-reduce: after xor8 + xor16, every lane holds
            // the full y of row (fg&1); lanes 0..15 store both rows.
            float s = __shfl_xor_sync(0xffffffffu, fb0 ? y0 : y1, 8);
            float p = (fb0 ? y1 : y0) + s;
            p += __shfl_xor_sync(0xffffffffu, p, 16);
            if (lane < 16) op[0] = p;
            op += 64;

            #pragma unroll
            for (int i = 0; i < 4; i++) { A0[i] = B0[i]; A1[i] = B1[i]; }
            za += 320;
        }

        // drain last pair (rows 30, 31)
        {
            float y0 = epi(A0, w2p, biaspack);
            float y1 = epi(A1, w2p, biaspack);
            float s = __shfl_xor_sync(0xffffffffu, fb0 ? y0 : y1, 8);
            float p = (fb0 ? y1 : y0) + s;
            p += __shfl_xor_sync(0xffffffffu, p, 16);
            if (lane < 16) op[0] = p;
        }

        if (!have_next) break;
        cp_wait_all();
        __syncthreads();
        buf ^= 1;
        tile = next;
    }
}

extern "C" void kernel_launch(void* const* d_in, const int* in_sizes, int n_in,
                              void* d_out, int out_size) {
    const float* x  = (const float*)d_in[0];
    const float* W1 = (const float*)d_in[1];
    const float* b1 = (const float*)d_in[2];
    const float* W2 = (const float*)d_in[3];
    const float* b2 = (const float*)d_in[4];
    // d_in[5] (idx) unused: circular window + np.nonzero sort order are
    // reproduced analytically (W1 k-rotation at register-load time).
    float* out = (float*)d_out;

    const int B = in_sizes[0] / 32;
    const int ntiles = B / 32;
    int grid = 148 * 4;                  // persistent, 4 blocks/SM
    if (grid > ntiles) grid = ntiles;
    fans_kernel<<<grid, TPB>>>(x, W1, b1, W2, b2, out, ntiles);
}